// round 3
// baseline (speedup 1.0000x reference)
#include <cuda_runtime.h>
#include <cstdint>

// ROIRotate: B=2048 boxes, crop 8x64x32 bilinear samples from (8,128,128,32) fp32
// feature map. Output: crops [B,8,64,32] fp32 followed by padded_width [B] fp32.

#define HEIGHT_  8
#define MAXW_    64
#define C_       32
#define H_       128
#define W_       128

__global__ void roi_rotate_kernel(const float* __restrict__ fm,
                                  const float* __restrict__ boxes,
                                  const int* __restrict__ box_idx,
                                  float* __restrict__ out_crops,
                                  float* __restrict__ out_pw)
{
    // one thread per (box, v, u, channel-quad). 8 quads cover C=32.
    // tid layout: b*4096 + v*512 + u*8 + c4  == float4 index into out_crops.
    const int tid = blockIdx.x * blockDim.x + threadIdx.x;
    const int c4 = tid & 7;
    const int u  = (tid >> 3) & 63;
    const int v  = (tid >> 9) & 7;
    const int b  = tid >> 12;   // grid sized exactly, no bound check needed

    // --- per-box geometry (redundant per thread; ALU-cheap) ---
    const float* bx = boxes + b * 9;
    const float x1 = bx[0] * 0.25f;
    const float y1 = bx[1] * 0.25f;
    const float x2 = bx[2] * 0.25f;
    const float y2 = bx[3] * 0.25f;
    const float x4 = bx[6] * 0.25f;
    const float y4 = bx[7] * 0.25f;

    const float box_w = x2 - x1;
    const float box_h = y4 - y1;
    float width = (float)HEIGHT_ * box_w / fmaxf(box_h, 1e-6f);
    width = fminf(fmaxf(width, 1.0f), (float)MAXW_);

    if ((tid & 4095) == 0) {            // v==0, u==0, c4==0
        out_pw[b] = (float)MAXW_ - width;
    }

    float4 res = make_float4(0.f, 0.f, 0.f, 0.f);

    if ((float)u < width) {
        const float tu = (float)u / width;
        const float tv = (float)v * (1.0f / (float)HEIGHT_);

        const float sx = x1 + tu * (x2 - x1) + tv * (x4 - x1);
        const float sy = y1 + tu * (y2 - y1) + tv * (y4 - y1);

        const float xf = floorf(sx);
        const float yf = floorf(sy);
        const float wx = sx - xf;
        const float wy = sy - yf;

        int x0i = min(max((int)xf, 0), W_ - 1);
        int x1i = min(x0i + 1, W_ - 1);
        int y0i = min(max((int)yf, 0), H_ - 1);
        int y1i = min(y0i + 1, H_ - 1);

        const int n = box_idx[b];
        const float* base = fm + (size_t)n * (H_ * W_ * C_) + (c4 << 2);

        const float4 g00 = *(const float4*)(base + (size_t)(y0i * W_ + x0i) * C_);
        const float4 g01 = *(const float4*)(base + (size_t)(y0i * W_ + x1i) * C_);
        const float4 g10 = *(const float4*)(base + (size_t)(y1i * W_ + x0i) * C_);
        const float4 g11 = *(const float4*)(base + (size_t)(y1i * W_ + x1i) * C_);

        const float w00 = (1.f - wy) * (1.f - wx);
        const float w01 = (1.f - wy) * wx;
        const float w10 = wy * (1.f - wx);
        const float w11 = wy * wx;

        res.x = w00 * g00.x + w01 * g01.x + w10 * g10.x + w11 * g11.x;
        res.y = w00 * g00.y + w01 * g01.y + w10 * g10.y + w11 * g11.y;
        res.z = w00 * g00.z + w01 * g01.z + w10 * g10.z + w11 * g11.z;
        res.w = w00 * g00.w + w01 * g01.w + w10 * g10.w + w11 * g11.w;
    }

    ((float4*)out_crops)[tid] = res;
}

extern "C" void kernel_launch(void* const* d_in, const int* in_sizes, int n_in,
                              void* d_out, int out_size)
{
    const float* fm    = (const float*)d_in[0];      // (8,128,128,32) f32
    const float* boxes = (const float*)d_in[1];      // (2048,9) f32
    const int*   bidx  = (const int*)d_in[2];        // (2048,) i32 (jax x64 disabled)

    const int B = in_sizes[1] / 9;                   // 2048

    float* out_crops = (float*)d_out;                // B*8*64*32 floats
    float* out_pw    = (float*)d_out + (size_t)B * HEIGHT_ * MAXW_ * C_;

    const int total_threads = B * HEIGHT_ * MAXW_ * (C_ / 4);  // 8,388,608
    const int block = 256;
    const int grid  = total_threads / block;

    roi_rotate_kernel<<<grid, block>>>(fm, boxes, bidx, out_crops, out_pw);
}

// round 4
// speedup vs baseline: 1.0584x; 1.0584x over previous
#include <cuda_runtime.h>
#include <cstdint>

// ROIRotate: B=2048 boxes, crop 8x64x32 bilinear samples from (8,128,128,32) fp32
// feature map. Output: crops [B,8,64,32] fp32 followed by padded_width [B] fp32.
//
// Two-kernel scheme:
//   1) box_prep: per-box geometry (incl. both fp32 divisions) -> scratch, writes pw.
//   2) roi_main: 2 channel-quads per thread, no division, minimal per-thread overhead.

#define HEIGHT_  8
#define MAXW_    64
#define C_       32
#define H_       128
#define W_       128
#define MAXB_    4096

__device__ float g_boxparams[MAXB_ * 8];   // x1,y1,dx21,dy21 | dx41,dy41,inv_w,width

__global__ void box_prep_kernel(const float* __restrict__ boxes,
                                int B,
                                float* __restrict__ out_pw)
{
    const int b = blockIdx.x * blockDim.x + threadIdx.x;
    if (b >= B) return;

    const float* bx = boxes + b * 9;
    const float x1 = bx[0] * 0.25f;
    const float y1 = bx[1] * 0.25f;
    const float x2 = bx[2] * 0.25f;
    const float y2 = bx[3] * 0.25f;
    const float x4 = bx[6] * 0.25f;
    const float y4 = bx[7] * 0.25f;

    const float box_w = x2 - x1;
    const float box_h = y4 - y1;
    float width = (float)HEIGHT_ * box_w / fmaxf(box_h, 1e-6f);
    width = fminf(fmaxf(width, 1.0f), (float)MAXW_);

    out_pw[b] = (float)MAXW_ - width;

    float4* s = (float4*)(g_boxparams + b * 8);
    s[0] = make_float4(x1, y1, x2 - x1, y2 - y1);
    s[1] = make_float4(x4 - x1, y4 - y1, 1.0f / width, width);
}

__global__ void roi_main_kernel(const float* __restrict__ fm,
                                const int* __restrict__ box_idx,
                                float* __restrict__ out_crops)
{
    // one thread per (box, v, u, channel-pair-of-quads).
    // tid = b*2048 + v*256 + u*4 + c2   (c2 in 0..3 covers quads 2*c2, 2*c2+1)
    const int tid = blockIdx.x * blockDim.x + threadIdx.x;
    const int c2 = tid & 3;
    const int u  = (tid >> 2) & 63;
    const int v  = (tid >> 8) & 7;
    const int b  = tid >> 11;

    const float4 p0 = ((const float4*)g_boxparams)[b * 2];      // x1,y1,dx21,dy21
    const float4 p1 = ((const float4*)g_boxparams)[b * 2 + 1];  // dx41,dy41,inv_w,width

    float4 r0 = make_float4(0.f, 0.f, 0.f, 0.f);
    float4 r1 = make_float4(0.f, 0.f, 0.f, 0.f);

    if ((float)u < p1.w) {
        const float tu = (float)u * p1.z;
        const float tv = (float)v * (1.0f / (float)HEIGHT_);

        const float sx = p0.x + tu * p0.z + tv * p1.x;
        const float sy = p0.y + tu * p0.w + tv * p1.y;

        const float xf = floorf(sx);
        const float yf = floorf(sy);
        const float wx = sx - xf;
        const float wy = sy - yf;

        int x0i = min(max((int)xf, 0), W_ - 1);
        int x1i = min(x0i + 1, W_ - 1);
        int y0i = min(max((int)yf, 0), H_ - 1);
        int y1i = min(y0i + 1, H_ - 1);

        const int n = box_idx[b];
        const float* base = fm + (size_t)n * (H_ * W_ * C_) + (c2 << 3);

        const float* a00 = base + (size_t)(y0i * W_ + x0i) * C_;
        const float* a01 = base + (size_t)(y0i * W_ + x1i) * C_;
        const float* a10 = base + (size_t)(y1i * W_ + x0i) * C_;
        const float* a11 = base + (size_t)(y1i * W_ + x1i) * C_;

        // 8 independent 16B loads -> high MLP
        const float4 g00a = *(const float4*)(a00);
        const float4 g00b = *(const float4*)(a00 + 4);
        const float4 g01a = *(const float4*)(a01);
        const float4 g01b = *(const float4*)(a01 + 4);
        const float4 g10a = *(const float4*)(a10);
        const float4 g10b = *(const float4*)(a10 + 4);
        const float4 g11a = *(const float4*)(a11);
        const float4 g11b = *(const float4*)(a11 + 4);

        const float w00 = (1.f - wy) * (1.f - wx);
        const float w01 = (1.f - wy) * wx;
        const float w10 = wy * (1.f - wx);
        const float w11 = wy * wx;

        r0.x = w00 * g00a.x + w01 * g01a.x + w10 * g10a.x + w11 * g11a.x;
        r0.y = w00 * g00a.y + w01 * g01a.y + w10 * g10a.y + w11 * g11a.y;
        r0.z = w00 * g00a.z + w01 * g01a.z + w10 * g10a.z + w11 * g11a.z;
        r0.w = w00 * g00a.w + w01 * g01a.w + w10 * g10a.w + w11 * g11a.w;

        r1.x = w00 * g00b.x + w01 * g01b.x + w10 * g10b.x + w11 * g11b.x;
        r1.y = w00 * g00b.y + w01 * g01b.y + w10 * g10b.y + w11 * g11b.y;
        r1.z = w00 * g00b.z + w01 * g01b.z + w10 * g10b.z + w11 * g11b.z;
        r1.w = w00 * g00b.w + w01 * g01b.w + w10 * g10b.w + w11 * g11b.w;
    }

    float4* dst = (float4*)out_crops + (size_t)tid * 2;
    dst[0] = r0;
    dst[1] = r1;
}

extern "C" void kernel_launch(void* const* d_in, const int* in_sizes, int n_in,
                              void* d_out, int out_size)
{
    const float* fm    = (const float*)d_in[0];      // (8,128,128,32) f32
    const float* boxes = (const float*)d_in[1];      // (2048,9) f32
    const int*   bidx  = (const int*)d_in[2];        // (2048,) i32 (jax x64 disabled)

    const int B = in_sizes[1] / 9;                   // 2048

    float* out_crops = (float*)d_out;                // B*8*64*32 floats
    float* out_pw    = (float*)d_out + (size_t)B * HEIGHT_ * MAXW_ * C_;

    box_prep_kernel<<<(B + 255) / 256, 256>>>(boxes, B, out_pw);

    const int total_threads = B * HEIGHT_ * MAXW_ * (C_ / 8);  // 4,194,304
    const int block = 256;
    const int grid  = total_threads / block;

    roi_main_kernel<<<grid, block>>>(fm, bidx, out_crops);
}

// round 5
// speedup vs baseline: 1.3532x; 1.2786x over previous
#include <cuda_runtime.h>
#include <cstdint>

// ROIRotate: B=2048 boxes, crop 8x64x32 bilinear samples from (8,128,128,32) fp32
// feature map. Output: crops [B,8,64,32] fp32 followed by padded_width [B] fp32.
//
// Boxes are axis-aligned (y2==y1, x4==x1): sx depends only on u, sy only on v.
// Lane layout: 8 c4-lanes cover one full 128B pixel line per LDG.128 (optimal
// wavefronts). Each thread handles two v values (v, v+4) sharing x-index math.

#define HEIGHT_  8
#define MAXW_    64
#define C_       32
#define H_       128
#define W_       128
#define MAXB_    4096

__device__ float g_boxparams[MAXB_ * 8]; // x1,y1,dx21,dy41 | inv_w,width,base_off(int),unused

__global__ void box_prep_kernel(const float* __restrict__ boxes,
                                const int* __restrict__ box_idx,
                                int B,
                                float* __restrict__ out_pw)
{
    const int b = blockIdx.x * blockDim.x + threadIdx.x;
    if (b >= B) return;

    const float* bx = boxes + b * 9;
    const float x1 = bx[0] * 0.25f;
    const float y1 = bx[1] * 0.25f;
    const float x2 = bx[2] * 0.25f;
    const float y4 = bx[7] * 0.25f;

    const float box_w = x2 - x1;
    const float box_h = y4 - y1;
    float width = (float)HEIGHT_ * box_w / fmaxf(box_h, 1e-6f);
    width = fminf(fmaxf(width, 1.0f), (float)MAXW_);

    out_pw[b] = (float)MAXW_ - width;

    const int base_off = box_idx[b] * (H_ * W_ * C_);

    float4* s = (float4*)(g_boxparams + b * 8);
    s[0] = make_float4(x1, y1, box_w, box_h);
    s[1] = make_float4(1.0f / width, width, __int_as_float(base_off), 0.0f);
}

__global__ void __launch_bounds__(256)
roi_main_kernel(const float* __restrict__ fm,
                float* __restrict__ out_crops)
{
    // tid = b*2048 + vp*512 + u*8 + c4 ; thread handles v=vp and v=vp+4.
    const int tid = blockIdx.x * blockDim.x + threadIdx.x;
    const int c4 = tid & 7;
    const int u  = (tid >> 3) & 63;
    const int vp = (tid >> 9) & 3;
    const int b  = tid >> 11;

    const float4 p0 = ((const float4*)g_boxparams)[b * 2];      // x1,y1,dx21,dy41
    const float4 p1 = ((const float4*)g_boxparams)[b * 2 + 1];  // inv_w,width,base_off

    float4 ra = make_float4(0.f, 0.f, 0.f, 0.f);
    float4 rb = make_float4(0.f, 0.f, 0.f, 0.f);

    if ((float)u < p1.y) {
        // x geometry (shared by both v values)
        const float tu = (float)u * p1.x;
        const float sx = p0.x + tu * p0.z;
        const float xf = floorf(sx);
        const float wx = sx - xf;
        const int x0i = min(max((int)xf, 0), W_ - 1);
        const int x1i = min(x0i + 1, W_ - 1);

        // y geometry for v = vp and v = vp+4
        const float tva = (float)vp       * (1.0f / (float)HEIGHT_);
        const float tvb = (float)(vp + 4) * (1.0f / (float)HEIGHT_);
        const float sya = p0.y + tva * p0.w;
        const float syb = p0.y + tvb * p0.w;
        const float yfa = floorf(sya);
        const float yfb = floorf(syb);
        const float wya = sya - yfa;
        const float wyb = syb - yfb;
        const int y0a = min(max((int)yfa, 0), H_ - 1);
        const int y1a = min(y0a + 1, H_ - 1);
        const int y0b = min(max((int)yfb, 0), H_ - 1);
        const int y1b = min(y0b + 1, H_ - 1);

        const float* base = fm + __float_as_int(p1.z) + (c4 << 2);

        // 8 independent full-line-cooperative LDG.128
        const float4 a00 = *(const float4*)(base + (y0a * W_ + x0i) * C_);
        const float4 a01 = *(const float4*)(base + (y0a * W_ + x1i) * C_);
        const float4 a10 = *(const float4*)(base + (y1a * W_ + x0i) * C_);
        const float4 a11 = *(const float4*)(base + (y1a * W_ + x1i) * C_);
        const float4 b00 = *(const float4*)(base + (y0b * W_ + x0i) * C_);
        const float4 b01 = *(const float4*)(base + (y0b * W_ + x1i) * C_);
        const float4 b10 = *(const float4*)(base + (y1b * W_ + x0i) * C_);
        const float4 b11 = *(const float4*)(base + (y1b * W_ + x1i) * C_);

        {
            const float w00 = (1.f - wya) * (1.f - wx);
            const float w01 = (1.f - wya) * wx;
            const float w10 = wya * (1.f - wx);
            const float w11 = wya * wx;
            ra.x = w00 * a00.x + w01 * a01.x + w10 * a10.x + w11 * a11.x;
            ra.y = w00 * a00.y + w01 * a01.y + w10 * a10.y + w11 * a11.y;
            ra.z = w00 * a00.z + w01 * a01.z + w10 * a10.z + w11 * a11.z;
            ra.w = w00 * a00.w + w01 * a01.w + w10 * a10.w + w11 * a11.w;
        }
        {
            const float w00 = (1.f - wyb) * (1.f - wx);
            const float w01 = (1.f - wyb) * wx;
            const float w10 = wyb * (1.f - wx);
            const float w11 = wyb * wx;
            rb.x = w00 * b00.x + w01 * b01.x + w10 * b10.x + w11 * b11.x;
            rb.y = w00 * b00.y + w01 * b01.y + w10 * b10.y + w11 * b11.y;
            rb.z = w00 * b00.z + w01 * b01.z + w10 * b10.z + w11 * b11.z;
            rb.w = w00 * b00.w + w01 * b01.w + w10 * b10.w + w11 * b11.w;
        }
    }

    // out pixel (b, v, u): float4 index = ((b*8 + v)*64 + u)*8 + c4
    float4* o = (float4*)out_crops;
    const int pa = ((b * 8 + vp)     * 64 + u) * 8 + c4;
    const int pb = ((b * 8 + vp + 4) * 64 + u) * 8 + c4;
    o[pa] = ra;
    o[pb] = rb;
}

extern "C" void kernel_launch(void* const* d_in, const int* in_sizes, int n_in,
                              void* d_out, int out_size)
{
    const float* fm    = (const float*)d_in[0];      // (8,128,128,32) f32
    const float* boxes = (const float*)d_in[1];      // (2048,9) f32
    const int*   bidx  = (const int*)d_in[2];        // (2048,) i32

    const int B = in_sizes[1] / 9;                   // 2048

    float* out_crops = (float*)d_out;
    float* out_pw    = (float*)d_out + (size_t)B * HEIGHT_ * MAXW_ * C_;

    box_prep_kernel<<<(B + 255) / 256, 256>>>(boxes, bidx, B, out_pw);

    const int total_threads = B * 4 * MAXW_ * (C_ / 4);  // 4,194,304
    const int block = 256;
    const int grid  = total_threads / block;

    roi_main_kernel<<<grid, block>>>(fm, out_crops);
}